// round 15
// baseline (speedup 1.0000x reference)
#include <cuda_runtime.h>
#include <cuda_bf16.h>

#define B_ROWS 131072
#define D_DIM 128
#define G_NUM 128
#define FBLOCKS 592   // 148 SMs x 4 co-resident blocks (GB300 has 152 SMs: margin)

__device__ int   g_part[FBLOCKS * G_NUM];
__device__ int   g_counts[G_NUM * 32];
__device__ int   g_cursor[G_NUM * 32];
__device__ int   g_offsets[G_NUM + 1];
__device__ int   g_bucket[B_ROWS];
__device__ float g_csum[G_NUM * D_DIM];
__device__ float g_dsum[G_NUM * 32];
__device__ int   g_bars[8];                       // zero-init; reset at end of every run
__device__ uint4 g_xb[(size_t)B_ROWS * 32];       // 67 MB bf16 scratch, bucket order

static __device__ __forceinline__ int bstart(int b) {
    return (int)((long long)b * B_ROWS / FBLOCKS);
}

__device__ __forceinline__ void grid_bar(int idx) {
    __syncthreads();
    if (threadIdx.x == 0) {
        __threadfence();
        atomicAdd(&g_bars[idx], 1);
        while (*(volatile int*)&g_bars[idx] < FBLOCKS) __nanosleep(64);
        __threadfence();
    }
    __syncthreads();
}

__device__ __forceinline__ int find_group(int row) {
    int lo = 0, hi = G_NUM;
    while (hi - lo > 1) {
        int mid = (lo + hi) >> 1;
        if (g_offsets[mid] <= row) lo = mid; else hi = mid;
    }
    return lo;
}

__device__ __forceinline__ uint4 pack_bf16(float4 a, float4 b) {
    __nv_bfloat162 h0 = __floats2bfloat162_rn(a.x, a.y);
    __nv_bfloat162 h1 = __floats2bfloat162_rn(a.z, a.w);
    __nv_bfloat162 h2 = __floats2bfloat162_rn(b.x, b.y);
    __nv_bfloat162 h3 = __floats2bfloat162_rn(b.z, b.w);
    uint4 u;
    u.x = *reinterpret_cast<unsigned*>(&h0);
    u.y = *reinterpret_cast<unsigned*>(&h1);
    u.z = *reinterpret_cast<unsigned*>(&h2);
    u.w = *reinterpret_cast<unsigned*>(&h3);
    return u;
}

__device__ __forceinline__ void dist2_from(uint4 u, float4 c4, float& d0, float& d1) {
    float2 f0 = __bfloat1622float2(*reinterpret_cast<__nv_bfloat162*>(&u.x));
    float2 f1 = __bfloat1622float2(*reinterpret_cast<__nv_bfloat162*>(&u.y));
    float2 f2 = __bfloat1622float2(*reinterpret_cast<__nv_bfloat162*>(&u.z));
    float2 f3 = __bfloat1622float2(*reinterpret_cast<__nv_bfloat162*>(&u.w));
    float dx = f0.x - c4.x, dy = f0.y - c4.y, dz = f1.x - c4.z, dw = f1.y - c4.w;
    d0 = dx * dx + dy * dy + dz * dz + dw * dw;
    dx = f2.x - c4.x; dy = f2.y - c4.y; dz = f3.x - c4.z; dw = f3.y - c4.w;
    d1 = dx * dx + dy * dy + dz * dz + dw * dw;
}

__global__ void __launch_bounds__(256, 4) k_mega(
    const float* __restrict__ X,
    const int* __restrict__ subject,
    const int* __restrict__ labels,
    float* __restrict__ out)
{
    int b = blockIdx.x, t = threadIdx.x, w = t >> 5, l = t & 31;
    __shared__ int   sc[G_NUM], sred[256], swsum[4], scnt_i[G_NUM], sbase[G_NUM];
    __shared__ float4 smf[8][32];
    __shared__ float cc[128];
    __shared__ float sd[128], ssrt[128], scnt2[128], scoc[128], sdot[128];
    __shared__ float sredf;

    int rs0 = bstart(b), re0 = bstart(b + 1);

    // ---- P0: histogram (per-block partials, atomic-free globally) ----
    if (t < G_NUM) sc[t] = 0;
    __syncthreads();
    for (int i = rs0 + t; i < re0; i += 256) {
        int g = subject[i] * 8 + labels[i];
        atomicAdd(&sc[g], 1);
    }
    __syncthreads();
    if (t < G_NUM) g_part[b * G_NUM + t] = sc[t];
    grid_bar(0);

    // ---- P1: block 0 reduces partials, scans, inits accumulators ----
    if (b == 0) {
        int grp = t & 127, half = t >> 7;
        int sum = 0;
        for (int j = half; j < FBLOCKS; j += 2) sum += g_part[j * G_NUM + grp];
        sred[t] = sum;
        __syncthreads();
        int cnt = 0;
        if (t < 128) { cnt = sred[t] + sred[t + 128]; g_counts[t * 32] = cnt; }
        int lane = t & 31, wid = t >> 5;
        int incl = cnt;
        #pragma unroll
        for (int o = 1; o < 32; o <<= 1) {
            int v = __shfl_up_sync(0xffffffff, incl, o);
            if (lane >= o) incl += v;
        }
        if (lane == 31 && wid < 4) swsum[wid] = incl;
        __syncthreads();
        if (t < 128) {
            int base = 0;
            for (int i = 0; i < wid; i++) base += swsum[i];
            int excl = base + incl - cnt;
            g_offsets[t] = excl;
            g_cursor[t * 32] = excl;
            if (t == 127) g_offsets[G_NUM] = excl + cnt;
            g_dsum[t * 32] = 0.0f;
        }
        float4* cz = (float4*)g_csum;
        for (int i = t; i < G_NUM * D_DIM / 4; i += 256)
            cz[i] = make_float4(0.f, 0.f, 0.f, 0.f);
    }
    grid_bar(1);

    // ---- P2: scatter (chunk <= 222 rows < 256 threads: one row/thread) ----
    {
        if (t < G_NUM) scnt_i[t] = 0;
        __syncthreads();
        int myg = -1, loc = 0, row = -1;
        for (int i = rs0 + t; i < re0; i += 256) {
            int g = subject[i] * 8 + labels[i];
            loc = atomicAdd(&scnt_i[g], 1);
            myg = g; row = i;
        }
        __syncthreads();
        if (t < G_NUM && scnt_i[t] > 0) sbase[t] = atomicAdd(&g_cursor[t * 32], scnt_i[t]);
        __syncthreads();
        if (row >= 0) g_bucket[sbase[myg] + loc] = row;
    }
    grid_bar(2);

    // ---- P3: centroid sums + bf16 scratch write (X read once, evict-first) ----
    {
        int rs = rs0, re = re0;
        int g = find_group(rs);
        while (rs < re) {
            int se = min(re, g_offsets[g + 1]);
            float4 acc = make_float4(0.f, 0.f, 0.f, 0.f);
            for (int r = rs + w; r < se; r += 32) {
                int p1 = min(r + 8, se - 1), p2 = min(r + 16, se - 1), p3 = min(r + 24, se - 1);
                float m1 = (r + 8 < se) ? 1.f : 0.f;
                float m2 = (r + 16 < se) ? 1.f : 0.f;
                float m3 = (r + 24 < se) ? 1.f : 0.f;
                int b0 = g_bucket[r], b1 = g_bucket[p1], b2 = g_bucket[p2], b3 = g_bucket[p3];
                const float4* q0 = (const float4*)(X + (size_t)b0 * 256);
                const float4* q1 = (const float4*)(X + (size_t)b1 * 256);
                const float4* q2 = (const float4*)(X + (size_t)b2 * 256);
                const float4* q3 = (const float4*)(X + (size_t)b3 * 256);
                float4 a00 = __ldcs(q0 + l), a01 = __ldcs(q0 + l + 32);
                float4 a10 = __ldcs(q1 + l), a11 = __ldcs(q1 + l + 32);
                float4 a20 = __ldcs(q2 + l), a21 = __ldcs(q2 + l + 32);
                float4 a30 = __ldcs(q3 + l), a31 = __ldcs(q3 + l + 32);
                g_xb[(size_t)r  * 32 + l] = pack_bf16(a00, a01);
                g_xb[(size_t)p1 * 32 + l] = pack_bf16(a10, a11);
                g_xb[(size_t)p2 * 32 + l] = pack_bf16(a20, a21);
                g_xb[(size_t)p3 * 32 + l] = pack_bf16(a30, a31);
                acc.x += (a00.x + a01.x) + m1 * (a10.x + a11.x) + m2 * (a20.x + a21.x) + m3 * (a30.x + a31.x);
                acc.y += (a00.y + a01.y) + m1 * (a10.y + a11.y) + m2 * (a20.y + a21.y) + m3 * (a30.y + a31.y);
                acc.z += (a00.z + a01.z) + m1 * (a10.z + a11.z) + m2 * (a20.z + a21.z) + m3 * (a30.z + a31.z);
                acc.w += (a00.w + a01.w) + m1 * (a10.w + a11.w) + m2 * (a20.w + a21.w) + m3 * (a30.w + a31.w);
            }
            smf[w][l] = acc;
            __syncthreads();
            if (w == 0) {
                float4 tot = smf[0][l];
                #pragma unroll
                for (int i = 1; i < 8; i++) {
                    float4 v = smf[i][l];
                    tot.x += v.x; tot.y += v.y; tot.z += v.z; tot.w += v.w;
                }
                float* dst = &g_csum[g * 128 + 4 * l];
                atomicAdd(dst + 0, tot.x);
                atomicAdd(dst + 1, tot.y);
                atomicAdd(dst + 2, tot.z);
                atomicAdd(dst + 3, tot.w);
            }
            __syncthreads();
            rs = se; g++;
        }
    }
    grid_bar(3);

    // ---- P4: distances from L2-resident bf16 scratch (mirrored block) ----
    {
        int mb = FBLOCKS - 1 - b;
        int rs = bstart(mb), re = bstart(mb + 1);
        int g = find_group(rs);
        while (rs < re) {
            int se = min(re, g_offsets[g + 1]);
            float cnt2 = 2.0f * (float)g_counts[g * 32];
            __syncthreads();
            if (t < 128) cc[t] = __ldcg(&g_csum[g * 128 + t]) / cnt2;
            __syncthreads();
            float4 c4 = ((const float4*)cc)[l];
            float s = 0.0f;
            for (int r = rs + w; r < se; r += 32) {
                int p1 = min(r + 8, se - 1), p2 = min(r + 16, se - 1), p3 = min(r + 24, se - 1);
                float m1 = (r + 8 < se) ? 1.f : 0.f;
                float m2 = (r + 16 < se) ? 1.f : 0.f;
                float m3 = (r + 24 < se) ? 1.f : 0.f;
                uint4 u0 = g_xb[(size_t)r  * 32 + l];
                uint4 u1 = g_xb[(size_t)p1 * 32 + l];
                uint4 u2 = g_xb[(size_t)p2 * 32 + l];
                uint4 u3 = g_xb[(size_t)p3 * 32 + l];
                float d[8];
                dist2_from(u0, c4, d[0], d[1]);
                dist2_from(u1, c4, d[2], d[3]);
                dist2_from(u2, c4, d[4], d[5]);
                dist2_from(u3, c4, d[6], d[7]);
                #pragma unroll
                for (int o = 16; o; o >>= 1) {
                    #pragma unroll
                    for (int k = 0; k < 8; k++) d[k] += __shfl_xor_sync(0xffffffff, d[k], o);
                }
                s += (sqrtf(sqrtf(d[0])) + sqrtf(sqrtf(d[1])))
                   + m1 * (sqrtf(sqrtf(d[2])) + sqrtf(sqrtf(d[3])))
                   + m2 * (sqrtf(sqrtf(d[4])) + sqrtf(sqrtf(d[5])))
                   + m3 * (sqrtf(sqrtf(d[6])) + sqrtf(sqrtf(d[7])));
            }
            if (l == 0) atomicAdd(&g_dsum[g * 32], s);
            rs = se; g++;
        }
    }
    grid_bar(4);

    // ---- P5: block 0 finalizes ----
    if (b == 0) {
        int g = t;
        bool act = g < 128;
        float cnt2 = 1.f, dens = 0.f;
        bool valid = false;
        if (act) {
            cnt2 = 2.0f * (float)g_counts[g * 32];
            scnt2[g] = cnt2;
            dens = (g_dsum[g * 32] / cnt2) / logf(cnt2 + 10.0f);
            valid = cnt2 > 1.0f;
            sd[g] = valid ? dens : 0.0f;
        }
        __syncthreads();
        if (t == 0) {
            float m = sd[0];
            for (int i = 1; i < 128; i++) m = fmaxf(m, sd[i]);
            sredf = m;
        }
        __syncthreads();
        if (act) { dens = valid ? dens : sredf; sd[g] = dens; }
        __syncthreads();
        if (act) {
            int rank = 0;
            for (int j = 0; j < 128; j++) {
                float v = sd[j];
                rank += (v < dens) || (v == dens && j < g);
            }
            ssrt[rank] = dens;
        }
        __syncthreads();
        if (act) {
            float lo = ssrt[12] + 0.7f * (ssrt[13] - ssrt[12]);
            float hi = ssrt[114] + 0.3f * (ssrt[115] - ssrt[114]);
            dens = fminf(fmaxf(dens, lo), hi);
            sd[g] = dens;
        }
        __syncthreads();
        if (t == 0) {
            float m = 0.0f;
            for (int i = 0; i < 128; i++) m += sd[i];
            sredf = m / 128.0f;
        }
        __syncthreads();
        if (act) {
            dens = 0.1f * dens / sredf;
            float coc = 0.0f;
            for (int j = 0; j < 128; j++) coc += g_csum[j * 128 + g] / scnt2[j];
            scoc[g] = coc * (1.0f / 128.0f);
        }
        __syncthreads();
        {
            int lane = t & 31, w8 = t >> 5;
            for (int j = w8; j < 128; j += 8) {
                const float* row = &g_csum[j * 128];
                float v = row[lane] * scoc[lane]
                        + row[lane + 32] * scoc[lane + 32]
                        + row[lane + 64] * scoc[lane + 64]
                        + row[lane + 96] * scoc[lane + 96];
                #pragma unroll
                for (int o = 16; o; o >>= 1) v += __shfl_xor_sync(0xffffffff, v, o);
                if (lane == 0) sdot[j] = v;
            }
        }
        __syncthreads();
        if (act) sd[g] = expf((sdot[g] / cnt2) / dens);
        __syncthreads();
        if (t == 0) {
            float m = sd[0], sum = 0.0f;
            for (int i = 0; i < 128; i++) {
                m = fmaxf(m, sd[i]);
                sum += sd[i];
            }
            out[0] = m - sum / 128.0f;
        }
        __syncthreads();
        if (t < 8) g_bars[t] = 0;   // reset for next replay (all blocks past bar 4)
    }
}

extern "C" void kernel_launch(void* const* d_in, const int* in_sizes, int n_in,
                              void* d_out, int out_size) {
    const float* X       = (const float*)d_in[0];
    const int*   subject = (const int*)d_in[1];
    const int*   labels  = (const int*)d_in[2];
    float*       out     = (float*)d_out;

    k_mega<<<FBLOCKS, 256>>>(X, subject, labels, out);
}